// round 14
// baseline (speedup 1.0000x reference)
#include <cuda_runtime.h>
#include <math.h>

#define IMG_W 512
#define IMG_H 512

// AAN (Arai-Agui-Nakajima) 8-point forward DCT, libjpeg jfdctflt flowgraph.
__device__ __forceinline__ void aan_dct8(float* d)
{
    float tmp0 = d[0] + d[7], tmp7 = d[0] - d[7];
    float tmp1 = d[1] + d[6], tmp6 = d[1] - d[6];
    float tmp2 = d[2] + d[5], tmp5 = d[2] - d[5];
    float tmp3 = d[3] + d[4], tmp4 = d[3] - d[4];

    float tmp10 = tmp0 + tmp3, tmp13 = tmp0 - tmp3;
    float tmp11 = tmp1 + tmp2, tmp12 = tmp1 - tmp2;

    d[0] = tmp10 + tmp11;
    d[4] = tmp10 - tmp11;

    float z1 = (tmp12 + tmp13) * 0.707106781f;
    d[2] = tmp13 + z1;
    d[6] = tmp13 - z1;

    tmp10 = tmp4 + tmp5;
    tmp11 = tmp5 + tmp6;
    tmp12 = tmp6 + tmp7;

    float z5 = (tmp10 - tmp12) * 0.382683433f;
    float z2 = fmaf(0.541196100f, tmp10, z5);
    float z4 = fmaf(1.306562965f, tmp12, z5);
    float z3 = tmp11 * 0.707106781f;

    float z11 = tmp7 + z3;
    float z13 = tmp7 - z3;

    d[5] = z13 + z2;
    d[3] = z13 - z2;
    d[1] = z11 + z4;
    d[7] = z11 - z4;
}

// In-register 8x8 transpose across an 8-lane group (12 shfl butterflies).
__device__ __forceinline__ void transpose8(float* d, int x)
{
    #pragma unroll
    for (int m = 1; m < 8; m <<= 1) {
        #pragma unroll
        for (int j0 = 0; j0 < 8; j0++) {
            if (j0 & m) continue;
            int j1 = j0 | m;
            float a   = (x & m) ? d[j0] : d[j1];
            float bsh = __shfl_xor_sync(0xffffffffu, a, m);
            if (x & m) d[j0] = bsh; else d[j1] = bsh;
        }
    }
}

__constant__ int c_yt[64] = {
    16,11,10,16,24,40,51,61, 12,12,14,19,26,58,60,55,
    14,13,16,24,40,57,69,56, 14,17,22,29,51,87,80,62,
    18,22,37,56,68,109,103,77, 24,35,55,64,81,104,113,92,
    49,64,78,87,103,121,120,101, 72,92,95,98,112,100,103,99};
__constant__ int c_ct[64] = {
    17,18,24,47,99,99,99,99, 18,21,26,66,99,99,99,99,
    24,26,56,99,99,99,99,99, 47,66,99,99,99,99,99,99,
    99,99,99,99,99,99,99,99, 99,99,99,99,99,99,99,99,
    99,99,99,99,99,99,99,99, 99,99,99,99,99,99,99,99};
__constant__ float c_asf[8] = {
    1.0f, 1.3870398453f, 1.3065629649f, 1.1758756024f,
    1.0f, 0.7856949583f, 0.5411961001f, 0.2758993792f};

// One CTA: 64(W) x 64(H) tile, 8 warps. Warp w owns band rows [8w, 8w+8):
// it loads the band, writes sY, __syncwarp()s, and DCTs its own 8 Y blocks
// without waiting for other warps. Only chroma (vertical 2x2 pooling crosses
// bands) uses the CTA-wide barrier.
__global__ void __launch_bounds__(256, 8)
jpeg_compress_kernel(const float* __restrict__ img, float* __restrict__ out)
{
    __shared__ float sY  [64][68];   // Y - 128, padded
    __shared__ float sCbP[32][36];   // pooled Cb (centered)
    __shared__ float sCrP[32][36];   // pooled Cr (centered)
    __shared__ float sQ  [128];      // quant reciprocal tables

    const int t       = threadIdx.x;
    const int w       = t >> 5;       // warp 0..7 = band index
    const int lane    = t & 31;
    const int tileCol = blockIdx.x;   // 0..7
    const int tileRow = blockIdx.y;   // 0..7
    const int b       = blockIdx.z;
    const int nbatch  = gridDim.z;

    // --- quant tables; barrier BEFORE any use (phase 3a reads pre-main-barrier) ---
    if (t < 64) {
        int uu = t >> 3, vv = t & 7;
        float sc = 1.0f / (8.0f * c_asf[uu] * c_asf[vv]);
        sQ[t]      = sc / (float)c_yt[t];
        sQ[64 + t] = sc / (float)c_ct[t];
    }
    __syncthreads();   // cheap: kernel start, all warps arrive immediately

    // --- Phase 1: warp w loads its 8x64 band (4 sub-iters of 2 rows) ---
    const size_t plane = (size_t)IMG_H * IMG_W;
    const float* base = img + (size_t)b * 3 * plane
                      + (size_t)(tileRow * 64 + w * 8) * IMG_W + tileCol * 64;
    const int rr  = lane >> 4;        // 0..1 row within pair
    const int c4  = (lane & 15) * 4;

    #pragma unroll 2
    for (int k = 0; k < 4; k++) {
        const int row = k * 2 + rr;   // 0..7 within band
        const float* sb = base + (size_t)row * IMG_W + c4;
        const float4 R4 = __ldcs(reinterpret_cast<const float4*>(sb));
        const float4 G4 = __ldcs(reinterpret_cast<const float4*>(sb + plane));
        const float4 B4 = __ldcs(reinterpret_cast<const float4*>(sb + 2 * plane));
        float Rv[4] = {R4.x, R4.y, R4.z, R4.w};
        float Gv[4] = {G4.x, G4.y, G4.z, G4.w};
        float Bv[4] = {B4.x, B4.y, B4.z, B4.w};
        float y[4], cb[4], cr[4];
        #pragma unroll
        for (int i = 0; i < 4; i++) {
            float R = Rv[i], G = Gv[i], B = Bv[i];
            y [i] =  76.245f    * R + 149.685f   * G + 29.07f     * B - 128.0f;
            cb[i] = -43.02768f  * R - 84.47232f  * G + 127.5f     * B;
            cr[i] =  127.5f     * R - 106.76544f * G - 20.73456f  * B;
        }
        *reinterpret_cast<float4*>(&sY[w * 8 + row][c4]) = make_float4(y[0], y[1], y[2], y[3]);

        // chroma pool: horizontal in-thread, vertical via partner lane^16 (row pair)
        float hcb0 = cb[0] + cb[1], hcb1 = cb[2] + cb[3];
        float hcr0 = cr[0] + cr[1], hcr1 = cr[2] + cr[3];
        float pcb0 = hcb0 + __shfl_xor_sync(0xffffffffu, hcb0, 16);
        float pcb1 = hcb1 + __shfl_xor_sync(0xffffffffu, hcb1, 16);
        float pcr0 = hcr0 + __shfl_xor_sync(0xffffffffu, hcr0, 16);
        float pcr1 = hcr1 + __shfl_xor_sync(0xffffffffu, hcr1, 16);
        if (!(lane & 16)) {
            int pr = w * 4 + k;             // pooled row 0..31
            int pc = (lane & 15) * 2;       // pooled col 0..30
            *reinterpret_cast<float2*>(&sCbP[pr][pc]) = make_float2(0.25f * pcb0, 0.25f * pcb1);
            *reinterpret_cast<float2*>(&sCrP[pr][pc]) = make_float2(0.25f * pcr0, 0.25f * pcr1);
        }
    }
    __syncwarp();   // band is warp-local: only this warp wrote sY[8w..8w+8)

    // --- Phase 3a: warp w DCTs its own 8 Y blocks (2 iters x 4 groups) ---
    const int gw = lane >> 3;   // group within warp 0..3
    const int x  = lane & 7;
    const int v  = x;

    #pragma unroll
    for (int iter = 0; iter < 2; iter++) {
        const int bx = iter * 4 + gw;      // 0..7 block within band

        float d[8];
        float4 a = *reinterpret_cast<const float4*>(&sY[w * 8 + x][bx * 8]);
        float4 c = *reinterpret_cast<const float4*>(&sY[w * 8 + x][bx * 8 + 4]);
        d[0]=a.x; d[1]=a.y; d[2]=a.z; d[3]=a.w;
        d[4]=c.x; d[5]=c.y; d[6]=c.z; d[7]=c.w;

        aan_dct8(d);
        transpose8(d, x);
        aan_dct8(d);

        int n = (tileRow * 8 + w) * 64 + (tileCol * 8 + bx);
        float* dst = out + (size_t)b * 4096 * 64 + (size_t)n * 64 + v;
        #pragma unroll
        for (int u = 0; u < 8; u++)
            __stcs(dst + u * 8, rintf(d[u] * sQ[u * 8 + v]));
    }

    __syncthreads();   // chroma blocks cross bands

    // --- Phase 3b: 32 chroma blocks (16 Cb + 16 Cr), one full 32-group pass ---
    {
        const int g    = t >> 3;              // 0..31
        const int comp = g >> 4;              // 0 = Cb, 1 = Cr
        const int idx  = g & 15;
        const int byc  = idx >> 2;            // 0..3
        const int bxc  = idx & 3;             // 0..3
        const float (*src)[36] = comp ? sCrP : sCbP;

        float d[8];
        float4 a = *reinterpret_cast<const float4*>(&src[byc * 8 + x][bxc * 8]);
        float4 c = *reinterpret_cast<const float4*>(&src[byc * 8 + x][bxc * 8 + 4]);
        d[0]=a.x; d[1]=a.y; d[2]=a.z; d[3]=a.w;
        d[4]=c.x; d[5]=c.y; d[6]=c.z; d[7]=c.w;

        aan_dct8(d);
        transpose8(d, x);
        aan_dct8(d);

        int n = (tileRow * 4 + byc) * 32 + (tileCol * 4 + bxc);
        size_t off = (size_t)nbatch * 4096 * 64
                   + (size_t)comp * nbatch * 1024 * 64
                   + (size_t)b * 1024 * 64 + (size_t)n * 64;
        float* dst = out + off + v;
        #pragma unroll
        for (int u = 0; u < 8; u++)
            __stcs(dst + u * 8, rintf(d[u] * sQ[64 + u * 8 + v]));
    }
}

extern "C" void kernel_launch(void* const* d_in, const int* in_sizes, int n_in,
                              void* d_out, int out_size)
{
    const float* img = (const float*)d_in[0];
    float* out = (float*)d_out;
    int nbatch = in_sizes[0] / (3 * IMG_H * IMG_W);
    dim3 grid(IMG_W / 64, IMG_H / 64, nbatch);
    jpeg_compress_kernel<<<grid, 256>>>(img, out);
}

// round 15
// speedup vs baseline: 1.1405x; 1.1405x over previous
#include <cuda_runtime.h>
#include <math.h>

#define IMG_W 512
#define IMG_H 512

// AAN (Arai-Agui-Nakajima) 8-point forward DCT, libjpeg jfdctflt flowgraph.
__device__ __forceinline__ void aan_dct8(float* d)
{
    float tmp0 = d[0] + d[7], tmp7 = d[0] - d[7];
    float tmp1 = d[1] + d[6], tmp6 = d[1] - d[6];
    float tmp2 = d[2] + d[5], tmp5 = d[2] - d[5];
    float tmp3 = d[3] + d[4], tmp4 = d[3] - d[4];

    float tmp10 = tmp0 + tmp3, tmp13 = tmp0 - tmp3;
    float tmp11 = tmp1 + tmp2, tmp12 = tmp1 - tmp2;

    d[0] = tmp10 + tmp11;
    d[4] = tmp10 - tmp11;

    float z1 = (tmp12 + tmp13) * 0.707106781f;
    d[2] = tmp13 + z1;
    d[6] = tmp13 - z1;

    tmp10 = tmp4 + tmp5;
    tmp11 = tmp5 + tmp6;
    tmp12 = tmp6 + tmp7;

    float z5 = (tmp10 - tmp12) * 0.382683433f;
    float z2 = fmaf(0.541196100f, tmp10, z5);
    float z4 = fmaf(1.306562965f, tmp12, z5);
    float z3 = tmp11 * 0.707106781f;

    float z11 = tmp7 + z3;
    float z13 = tmp7 - z3;

    d[5] = z13 + z2;
    d[3] = z13 - z2;
    d[1] = z11 + z4;
    d[7] = z11 - z4;
}

// In-register 8x8 transpose across an 8-lane group (12 shfl butterflies).
__device__ __forceinline__ void transpose8(float* d, int x)
{
    #pragma unroll
    for (int m = 1; m < 8; m <<= 1) {
        #pragma unroll
        for (int j0 = 0; j0 < 8; j0++) {
            if (j0 & m) continue;
            int j1 = j0 | m;
            float a   = (x & m) ? d[j0] : d[j1];
            float bsh = __shfl_xor_sync(0xffffffffu, a, m);
            if (x & m) d[j0] = bsh; else d[j1] = bsh;
        }
    }
}

__constant__ int c_yt[64] = {
    16,11,10,16,24,40,51,61, 12,12,14,19,26,58,60,55,
    14,13,16,24,40,57,69,56, 14,17,22,29,51,87,80,62,
    18,22,37,56,68,109,103,77, 24,35,55,64,81,104,113,92,
    49,64,78,87,103,121,120,101, 72,92,95,98,112,100,103,99};
__constant__ int c_ct[64] = {
    17,18,24,47,99,99,99,99, 18,21,26,66,99,99,99,99,
    24,26,56,99,99,99,99,99, 47,66,99,99,99,99,99,99,
    99,99,99,99,99,99,99,99, 99,99,99,99,99,99,99,99,
    99,99,99,99,99,99,99,99, 99,99,99,99,99,99,99,99};
__constant__ float c_asf[8] = {
    1.0f, 1.3870398453f, 1.3065629649f, 1.1758756024f,
    1.0f, 0.7856949583f, 0.5411961001f, 0.2758993792f};

// One CTA: 64(W) x 16(H) pixel tile, 128 threads (16 CTAs/SM for fine-grained
// load/compute interleaving across CTAs). -> 16 Y + 4 Cb + 4 Cr blocks.
__global__ void __launch_bounds__(128, 16)
jpeg_compress_kernel(const float* __restrict__ img, float* __restrict__ out)
{
    __shared__ float sY  [16][68];   // Y - 128, padded
    __shared__ float sCbP[8][36];    // pooled Cb (centered)
    __shared__ float sCrP[8][36];    // pooled Cr (centered)
    __shared__ float sQ  [128];      // quant reciprocal tables

    const int t       = threadIdx.x;
    const int tileCol = blockIdx.x;   // 0..7   (64-px cols)
    const int tileRow = blockIdx.y;   // 0..31  (16-px rows)
    const int b       = blockIdx.z;
    const int nbatch  = gridDim.z;

    // --- quant tables (pure fp32); covered by the phase-1 barrier below ---
    if (t < 64) {
        int uu = t >> 3, vv = t & 7;
        float sc = 1.0f / (8.0f * c_asf[uu] * c_asf[vv]);
        sQ[t]      = sc / (float)c_yt[t];
        sQ[64 + t] = sc / (float)c_ct[t];
    }

    // --- Phase 1: two 64x8 subtiles; streaming loads; x255 folded into coefs ---
    const size_t plane = (size_t)IMG_H * IMG_W;
    const float* base = img + (size_t)b * 3 * plane
                      + (size_t)(tileRow * 16) * IMG_W + tileCol * 64;
    const int r  = t >> 4;           // 0..7 (row within subtile; partner t^16 -> r^1)
    const int c4 = (t & 15) * 4;

    #pragma unroll
    for (int s = 0; s < 2; s++) {
        const float* sb = base + (size_t)(s * 8 + r) * IMG_W + c4;
        const float4 R4 = __ldcs(reinterpret_cast<const float4*>(sb));
        const float4 G4 = __ldcs(reinterpret_cast<const float4*>(sb + plane));
        const float4 B4 = __ldcs(reinterpret_cast<const float4*>(sb + 2 * plane));
        float Rv[4] = {R4.x, R4.y, R4.z, R4.w};
        float Gv[4] = {G4.x, G4.y, G4.z, G4.w};
        float Bv[4] = {B4.x, B4.y, B4.z, B4.w};
        float y[4], cb[4], cr[4];
        #pragma unroll
        for (int i = 0; i < 4; i++) {
            float R = Rv[i], G = Gv[i], B = Bv[i];
            y [i] =  76.245f    * R + 149.685f   * G + 29.07f     * B - 128.0f;
            cb[i] = -43.02768f  * R - 84.47232f  * G + 127.5f     * B;
            cr[i] =  127.5f     * R - 106.76544f * G - 20.73456f  * B;
        }
        *reinterpret_cast<float4*>(&sY[s * 8 + r][c4]) = make_float4(y[0], y[1], y[2], y[3]);

        // horizontal pool in regs, vertical pool via shfl with partner row (lane ^ 16)
        float hcb0 = cb[0] + cb[1], hcb1 = cb[2] + cb[3];
        float hcr0 = cr[0] + cr[1], hcr1 = cr[2] + cr[3];
        float pcb0 = hcb0 + __shfl_xor_sync(0xffffffffu, hcb0, 16);
        float pcb1 = hcb1 + __shfl_xor_sync(0xffffffffu, hcb1, 16);
        float pcr0 = hcr0 + __shfl_xor_sync(0xffffffffu, hcr0, 16);
        float pcr1 = hcr1 + __shfl_xor_sync(0xffffffffu, hcr1, 16);
        if (!(t & 16)) {
            int pr = s * 4 + (r >> 1);   // pooled row 0..7
            int pc = (t & 15) * 2;
            *reinterpret_cast<float2*>(&sCbP[pr][pc]) = make_float2(0.25f * pcb0, 0.25f * pcb1);
            *reinterpret_cast<float2*>(&sCrP[pr][pc]) = make_float2(0.25f * pcr0, 0.25f * pcr1);
        }
    }
    __syncthreads();

    // --- Phase 3: 16 groups of 8 lanes ---
    const int g = t >> 3;   // group 0..15
    const int x = t & 7;
    const int v = x;

    // ---- Iter 1: 16 Y blocks (by = g>>3, bx = g&7) — all threads active ----
    {
        const int by = g >> 3, bx = g & 7;
        float d[8];
        float4 a = *reinterpret_cast<const float4*>(&sY[by * 8 + x][bx * 8]);
        float4 c = *reinterpret_cast<const float4*>(&sY[by * 8 + x][bx * 8 + 4]);
        d[0]=a.x; d[1]=a.y; d[2]=a.z; d[3]=a.w;
        d[4]=c.x; d[5]=c.y; d[6]=c.z; d[7]=c.w;

        aan_dct8(d);
        transpose8(d, x);
        aan_dct8(d);

        int n = (tileRow * 2 + by) * 64 + (tileCol * 8 + bx);
        float* dst = out + (size_t)b * 4096 * 64 + (size_t)n * 64 + v;
        #pragma unroll
        for (int u = 0; u < 8; u++)
            __stcs(dst + u * 8, rintf(d[u] * sQ[u * 8 + v]));
    }

    // ---- Iter 2: 8 chroma blocks. Groups g and g+8 BOTH compute block (g&7)'s
    //      DCT (redundant, free — those lanes were idle) and split the 8 store
    //      rows between them, halving the store tail. ----
    {
        const int blkc = g & 7;           // chroma block 0..7
        const int half = g >> 3;          // 0: stores u=0..3, 1: stores u=4..7
        const int comp = blkc >> 2;       // 0 = Cb, 1 = Cr
        const int bxc  = blkc & 3;        // 0..3
        const float (*src)[36] = comp ? sCrP : sCbP;

        float d[8];
        float4 a = *reinterpret_cast<const float4*>(&src[x][bxc * 8]);
        float4 c = *reinterpret_cast<const float4*>(&src[x][bxc * 8 + 4]);
        d[0]=a.x; d[1]=a.y; d[2]=a.z; d[3]=a.w;
        d[4]=c.x; d[5]=c.y; d[6]=c.z; d[7]=c.w;

        aan_dct8(d);
        transpose8(d, x);
        aan_dct8(d);

        int n = tileRow * 32 + tileCol * 4 + bxc;
        size_t off = (size_t)nbatch * 4096 * 64
                   + (size_t)comp * nbatch * 1024 * 64
                   + (size_t)b * 1024 * 64 + (size_t)n * 64;
        float* dst = out + off + v;
        #pragma unroll
        for (int uu = 0; uu < 4; uu++) {
            int u = half * 4 + uu;
            __stcs(dst + u * 8, rintf(d[u] * sQ[64 + u * 8 + v]));
        }
    }
}

extern "C" void kernel_launch(void* const* d_in, const int* in_sizes, int n_in,
                              void* d_out, int out_size)
{
    const float* img = (const float*)d_in[0];
    float* out = (float*)d_out;
    int nbatch = in_sizes[0] / (3 * IMG_H * IMG_W);
    dim3 grid(IMG_W / 64, IMG_H / 16, nbatch);
    jpeg_compress_kernel<<<grid, 128>>>(img, out);
}